// round 5
// baseline (speedup 1.0000x reference)
#include <cuda_runtime.h>
#include <cuda_fp16.h>
#include <math.h>

typedef unsigned long long ull;

// ---------------- problem constants ----------------
#define NB       64
#define NNODES   1296        // 16*81
#define NC       43
#define OD       16
#define CO_TIMES_OD 688      // 43*16
#define CO4      172         // 688/4

// packed f32x2 FMA (Blackwell sm_103a): two fp32 MACs per instruction, bit-exact fp32
#define FMA2(a,x,y) asm("fma.rn.f32x2 %0, %1, %2, %0;" : "+l"(a) : "l"(x), "l"(y))

static __device__ __forceinline__ float f2lo(ull v){ return __uint_as_float((unsigned)v); }
static __device__ __forceinline__ float f2hi(ull v){ return __uint_as_float((unsigned)(v>>32)); }
static __device__ __forceinline__ ull pack2(float w){ ull r; asm("mov.b64 %0, {%1, %1};" : "=l"(r) : "f"(w)); return r; }

// ---------------- device scratch ----------------
__device__ float  g_w1t[62208];                    // conv1 weights scalar: [(ci*9+ky)*9+kx][co]
__device__ float  g_w2t[2097152];                  // prim  weights scalar: [(g*8+ky)*8+kx][co]
__device__ float  g_h[NB * 256 * 24 * 24];         // conv1 output (relu'd)
__device__ float  g_u[NB * NNODES * 8];            // primary capsules (squashed in place)
__device__ ull    g_pri[(size_t)NB * NNODES * CO4];// priors, fp16x4 packed (114MB)
__device__ float  g_logits[NB * NNODES * NC];
__device__ float  g_s[NB * CO_TIMES_OD];
__device__ float  g_caps[NB * CO_TIMES_OD];

static __device__ __forceinline__ unsigned h2u(__half2 h){ return *reinterpret_cast<unsigned*>(&h); }
static __device__ __forceinline__ __half2 u2h(unsigned u){ return *reinterpret_cast<__half2*>(&u); }

static __device__ __forceinline__ float4 unpk(ull v) {
    float2 a = __half22float2(u2h((unsigned)v));
    float2 b = __half22float2(u2h((unsigned)(v >> 32)));
    return make_float4(a.x, a.y, b.x, b.y);
}

// ---------------- weight transposes (scalar, co-major for coalesced loads) ----------------
__global__ void k_tr1(const float* __restrict__ w) {
    int idx = blockIdx.x * 256 + threadIdx.x;
    if (idx >= 62208) return;
    int co = idx & 255; int r = idx >> 8;      // r = (ci*9+ky)*9+kx, 0..242
    int kx = r % 9; int t = r / 9; int ky = t % 9; int ci = t / 9;
    g_w1t[idx] = w[co * 243 + ci * 81 + ky * 9 + kx];
}
__global__ void k_tr2(const float* __restrict__ w) {
    int idx = blockIdx.x * 256 + threadIdx.x;   // 2,097,152 exact
    int co = idx & 127;
    int kx = (idx >> 7) & 7;
    int ky = (idx >> 10) & 7;
    int g  = idx >> 13;
    g_w2t[idx] = w[co * 16384 + g * 64 + ky * 8 + kx];
}

// ---------------- conv1: batch-paired f32x2, (64,3,32,32) -> (64,256,24,24) ----------------
__global__ __launch_bounds__(256, 2) void k_conv1(const float* __restrict__ x,
                                                  const float* __restrict__ bias) {
    int oy = blockIdx.x, bp = blockIdx.y;
    int b0 = bp, b1 = bp + 32;
    int co = threadIdx.x;
    __shared__ float2 xs[864];           // [3 ci][9 r][32 col], pair (b0,b1)
    for (int idx = co; idx < 864; idx += 256) {
        int ci = idx / 288, rem = idx - ci * 288;
        int r = rem >> 5, col = rem & 31;
        int off = (ci * 32 + oy + r) * 32 + col;
        xs[idx] = make_float2(x[b0 * 3072 + off], x[b1 * 3072 + off]);
    }
    __syncthreads();
    const ull* xsu = (const ull*)xs;
    float bv = bias[co];
#pragma unroll 1
    for (int h = 0; h < 2; h++) {        // two halves of the 24-wide output row
        ull acc[12];
#pragma unroll
        for (int i = 0; i < 12; i++) acc[i] = 0ull;
        for (int ci = 0; ci < 3; ci++) {
#pragma unroll
            for (int ky = 0; ky < 9; ky++) {
                ull in[20];
                const ulonglong2* ip = (const ulonglong2*)(xsu + ci * 288 + ky * 32 + h * 12);
#pragma unroll
                for (int j = 0; j < 10; j++) { ulonglong2 t = ip[j]; in[2*j] = t.x; in[2*j+1] = t.y; }
                const float* wp = &g_w1t[((ci * 9 + ky) * 9) * 256 + co];
                ull w[9];
#pragma unroll
                for (int kx = 0; kx < 9; kx++) w[kx] = pack2(wp[kx * 256]);
#pragma unroll
                for (int kx = 0; kx < 9; kx++)
#pragma unroll
                    for (int ox = 0; ox < 12; ox++)
                        FMA2(acc[ox], in[ox + kx], w[kx]);
            }
        }
        float* h0 = &g_h[((b0 * 256 + co) * 24 + oy) * 24 + h * 12];
        float* h1 = &g_h[((b1 * 256 + co) * 24 + oy) * 24 + h * 12];
#pragma unroll
        for (int ox = 0; ox < 12; ox++) {
            h0[ox] = fmaxf(f2lo(acc[ox]) + bv, 0.f);
            h1[ox] = fmaxf(f2hi(acc[ox]) + bv, 0.f);
        }
    }
}

// ---------------- prim conv: 4 batches (2 f32x2 pairs) per block to halve weight L2 traffic ----------------
__global__ __launch_bounds__(256, 2) void k_prim(const float* __restrict__ bias) {
    int oy = blockIdx.x, bq = blockIdx.y;     // grid (9, 16)
    int b0 = bq, b1 = bq + 16, b2 = bq + 32, b3 = bq + 48;
    int tid = threadIdx.x;
    int kh = tid >> 7;          // K-range half
    int co = tid & 127;
    __shared__ float2 hs[2][3072];   // 48KB: [pair][16 ci][8 r][24 col]
    ull acc0[9], acc1[9];
#pragma unroll
    for (int i = 0; i < 9; i++) { acc0[i] = 0ull; acc1[i] = 0ull; }

    for (int cc = 0; cc < 16; cc++) {      // 16 chunks of 16 input channels
        __syncthreads();
        for (int idx = tid; idx < 3072; idx += 256) {
            int ci = idx / 192, rem = idx - ci * 192;
            int r = rem / 24, col = rem - r * 24;
            int off = ((cc * 16 + ci) * 24 + 2 * oy + r) * 24 + col;
            hs[0][idx] = make_float2(g_h[b0 * 147456 + off], g_h[b2 * 147456 + off]);
            hs[1][idx] = make_float2(g_h[b1 * 147456 + off], g_h[b3 * 147456 + off]);
        }
        __syncthreads();
        for (int cil = kh * 8; cil < kh * 8 + 8; cil++) {
            int g = cc * 16 + cil;
#pragma unroll
            for (int ky = 0; ky < 8; ky++) {
                const float* wp = &g_w2t[((g * 8 + ky) * 8) * 128 + co];
                ull w[8];
#pragma unroll
                for (int kx = 0; kx < 8; kx++) w[kx] = pack2(wp[kx * 128]);
                // pair 0
                {
                    ull in[24];
                    const ulonglong2* ip = (const ulonglong2*)((const ull*)&hs[0][cil * 192 + ky * 24]);
#pragma unroll
                    for (int j = 0; j < 12; j++) { ulonglong2 t = ip[j]; in[2*j] = t.x; in[2*j+1] = t.y; }
#pragma unroll
                    for (int kx = 0; kx < 8; kx++)
#pragma unroll
                        for (int ox = 0; ox < 9; ox++)
                            FMA2(acc0[ox], in[2 * ox + kx], w[kx]);
                }
                // pair 1
                {
                    ull in[24];
                    const ulonglong2* ip = (const ulonglong2*)((const ull*)&hs[1][cil * 192 + ky * 24]);
#pragma unroll
                    for (int j = 0; j < 12; j++) { ulonglong2 t = ip[j]; in[2*j] = t.x; in[2*j+1] = t.y; }
#pragma unroll
                    for (int kx = 0; kx < 8; kx++)
#pragma unroll
                        for (int ox = 0; ox < 9; ox++)
                            FMA2(acc1[ox], in[2 * ox + kx], w[kx]);
                }
            }
        }
    }
    __syncthreads();
    ull* cm = (ull*)hs;          // [pair*128 + co][9]
    if (kh == 1) {
#pragma unroll
        for (int ox = 0; ox < 9; ox++) {
            cm[(0 * 128 + co) * 9 + ox] = acc0[ox];
            cm[(1 * 128 + co) * 9 + ox] = acc1[ox];
        }
    }
    __syncthreads();
    if (kh == 0) {
        float bv = bias[co];
        int i = co >> 4, g2 = co & 15;
#pragma unroll
        for (int ox = 0; ox < 9; ox++) {
            int n = g2 * 81 + oy * 9 + ox;
            ull o0 = cm[(0 * 128 + co) * 9 + ox];
            ull o1 = cm[(1 * 128 + co) * 9 + ox];
            g_u[(b0 * NNODES + n) * 8 + i] = f2lo(acc0[ox]) + f2lo(o0) + bv;
            g_u[(b2 * NNODES + n) * 8 + i] = f2hi(acc0[ox]) + f2hi(o0) + bv;
            g_u[(b1 * NNODES + n) * 8 + i] = f2lo(acc1[ox]) + f2lo(o1) + bv;
            g_u[(b3 * NNODES + n) * 8 + i] = f2hi(acc1[ox]) + f2hi(o1) + bv;
        }
    }
}

// ---------------- squash primary capsules (dim 8, in place) ----------------
__global__ void k_squash_u() {
    int node = blockIdx.x * 256 + threadIdx.x;
    if (node >= NB * NNODES) return;
    float v[8]; float sn = 0.f;
#pragma unroll
    for (int i = 0; i < 8; i++) { v[i] = g_u[node * 8 + i]; sn = fmaf(v[i], v[i], sn); }
    float f = sqrtf(sn) / (1.f + sn);
#pragma unroll
    for (int i = 0; i < 8; i++) g_u[node * 8 + i] = v[i] * f;
}

// ---------------- priors[b,n,c,o] = sum_i u[b,n,i] * W[n,c,i,o]; store fp16x4 ----------------
__global__ __launch_bounds__(256) void k_priors(const float* __restrict__ route_w) {
    int n = blockIdx.x, tid = threadIdx.x;
    __shared__ float rw[NC * 8 * OD];   // 5504
    __shared__ float us[NB * 8];        // 512
    for (int idx = tid; idx < 5504; idx += 256) rw[idx] = route_w[n * 5504 + idx];
    for (int idx = tid; idx < 512; idx += 256) {
        int b = idx >> 3, i = idx & 7;
        us[idx] = g_u[(b * NNODES + n) * 8 + i];
    }
    __syncthreads();
    if (tid < CO4) {
        int c = tid >> 2;
        int obase = (tid & 3) * 4;
        const float* rwc = &rw[c * 128 + obase];
        for (int b = 0; b < NB; b++) {
            const float* ub = &us[b * 8];
            float4 sum = make_float4(0.f, 0.f, 0.f, 0.f);
#pragma unroll
            for (int i = 0; i < 8; i++) {
                float u = ub[i];
                sum.x = fmaf(u, rwc[i * 16 + 0], sum.x);
                sum.y = fmaf(u, rwc[i * 16 + 1], sum.y);
                sum.z = fmaf(u, rwc[i * 16 + 2], sum.z);
                sum.w = fmaf(u, rwc[i * 16 + 3], sum.w);
            }
            __half2 p01 = __floats2half2_rn(sum.x, sum.y);
            __half2 p23 = __floats2half2_rn(sum.z, sum.w);
            ull v = (ull)h2u(p01) | ((ull)h2u(p23) << 32);
            g_pri[(size_t)(b * NNODES + n) * CO4 + tid] = v;
        }
    }
}

// ---------------- zero s (start of pipeline only) ----------------
__global__ void k_zero_s() {
    int i = blockIdx.x * 256 + threadIdx.x;
    if (i < NB * CO_TIMES_OD) g_s[i] = 0.f;
}

// ---------------- iter0: s = sum_n priors (uniform probs folded into squash scale) ----------------
__global__ void k_reduce0() {
    int b = blockIdx.y, n0 = blockIdx.x * 81, tid = threadIdx.x;
    if (tid >= CO4) return;
    float4 acc = make_float4(0.f, 0.f, 0.f, 0.f);
    const ull* p = &g_pri[(size_t)(b * NNODES + n0) * CO4 + tid];
    for (int nn = 0; nn < 81; nn++) {
        float4 q = unpk(p[(size_t)nn * CO4]);
        acc.x += q.x; acc.y += q.y; acc.z += q.z; acc.w += q.w;
    }
    float* sp = &g_s[b * CO_TIMES_OD + tid * 4];
    atomicAdd(sp + 0, acc.x); atomicAdd(sp + 1, acc.y);
    atomicAdd(sp + 2, acc.z); atomicAdd(sp + 3, acc.w);
}

// ---------------- squash s -> output capsules, then reset s to 0 for next iteration ----------------
__global__ void k_squash_out(float scale) {
    int idx = blockIdx.x * 256 + threadIdx.x;
    if (idx >= NB * NC) return;
    float v[16]; float sn = 0.f;
#pragma unroll
    for (int o = 0; o < 16; o++) { v[o] = g_s[idx * 16 + o] * scale; sn = fmaf(v[o], v[o], sn); }
    float f = sqrtf(sn) / (1.f + sn);
#pragma unroll
    for (int o = 0; o < 16; o++) { g_caps[idx * 16 + o] = v[o] * f; g_s[idx * 16 + o] = 0.f; }
}

// ---------------- routing iteration: warp-per-node, lane = class ----------------
__global__ __launch_bounds__(256) void k_iter(int first) {
    int b = blockIdx.y;
    int lane = threadIdx.x & 31;
    int widx = blockIdx.x * 8 + (threadIdx.x >> 5);   // 0..15
    int nbase = widx * 81;
    int c1 = lane;
    bool has2 = lane < (NC - 32);     // lanes 0..10 carry class 32+lane
    int c2 = lane + 32;

    const float* cb = &g_caps[b * CO_TIMES_OD];
    float cap1[16], cap2[16];
#pragma unroll
    for (int o = 0; o < 16; o++) cap1[o] = cb[c1 * OD + o];
#pragma unroll
    for (int o = 0; o < 16; o++) cap2[o] = has2 ? cb[c2 * OD + o] : 0.f;

    float acc1[16], acc2[16];
#pragma unroll
    for (int o = 0; o < 16; o++) { acc1[o] = 0.f; acc2[o] = 0.f; }

    for (int nn = 0; nn < 81; nn++) {
        int n = nbase + nn;
        const ull* pp = &g_pri[((size_t)b * NNODES + n) * CO4];
        float pr1[16], pr2[16];
        {
            ulonglong2 q0 = *(const ulonglong2*)(pp + 4 * c1);
            ulonglong2 q1 = *(const ulonglong2*)(pp + 4 * c1 + 2);
            float4 a0 = unpk(q0.x), a1 = unpk(q0.y), a2 = unpk(q1.x), a3 = unpk(q1.y);
            pr1[0]=a0.x; pr1[1]=a0.y; pr1[2]=a0.z; pr1[3]=a0.w;
            pr1[4]=a1.x; pr1[5]=a1.y; pr1[6]=a1.z; pr1[7]=a1.w;
            pr1[8]=a2.x; pr1[9]=a2.y; pr1[10]=a2.z; pr1[11]=a2.w;
            pr1[12]=a3.x; pr1[13]=a3.y; pr1[14]=a3.z; pr1[15]=a3.w;
        }
        if (has2) {
            ulonglong2 q0 = *(const ulonglong2*)(pp + 4 * c2);
            ulonglong2 q1 = *(const ulonglong2*)(pp + 4 * c2 + 2);
            float4 a0 = unpk(q0.x), a1 = unpk(q0.y), a2 = unpk(q1.x), a3 = unpk(q1.y);
            pr2[0]=a0.x; pr2[1]=a0.y; pr2[2]=a0.z; pr2[3]=a0.w;
            pr2[4]=a1.x; pr2[5]=a1.y; pr2[6]=a1.z; pr2[7]=a1.w;
            pr2[8]=a2.x; pr2[9]=a2.y; pr2[10]=a2.z; pr2[11]=a2.w;
            pr2[12]=a3.x; pr2[13]=a3.y; pr2[14]=a3.z; pr2[15]=a3.w;
        } else {
#pragma unroll
            for (int o = 0; o < 16; o++) pr2[o] = 0.f;
        }
        float d1 = 0.f, d2 = 0.f;
#pragma unroll
        for (int o = 0; o < 16; o++) { d1 = fmaf(pr1[o], cap1[o], d1); d2 = fmaf(pr2[o], cap2[o], d2); }

        int L = (b * NNODES + n) * NC;
        float l1, l2;
        if (first) {
            l1 = d1; l2 = d2;
            g_logits[L + c1] = l1;
            if (has2) g_logits[L + c2] = l2;
        } else {
            l1 = g_logits[L + c1] + d1;
            l2 = has2 ? g_logits[L + c2] + d2 : -1e30f;
        }
        float mloc = has2 ? fmaxf(l1, l2) : l1;
#pragma unroll
        for (int off = 16; off; off >>= 1) mloc = fmaxf(mloc, __shfl_xor_sync(0xffffffffu, mloc, off));
        float e1 = __expf(l1 - mloc);
        float e2 = has2 ? __expf(l2 - mloc) : 0.f;
        float ss = e1 + e2;
#pragma unroll
        for (int off = 16; off; off >>= 1) ss += __shfl_xor_sync(0xffffffffu, ss, off);
        float inv = 1.f / ss;
        float p1 = e1 * inv, p2 = e2 * inv;
#pragma unroll
        for (int o = 0; o < 16; o++) { acc1[o] = fmaf(p1, pr1[o], acc1[o]); acc2[o] = fmaf(p2, pr2[o], acc2[o]); }
    }
    float* sb = &g_s[b * CO_TIMES_OD];
#pragma unroll
    for (int o = 0; o < 16; o++) atomicAdd(sb + c1 * OD + o, acc1[o]);
    if (has2) {
#pragma unroll
        for (int o = 0; o < 16; o++) atomicAdd(sb + c2 * OD + o, acc2[o]);
    }
}

// ---------------- final: scores = ||squash(s)|| = sn/(1+sn) ----------------
__global__ void k_final(float* __restrict__ out) {
    int idx = blockIdx.x * 256 + threadIdx.x;
    if (idx >= NB * NC) return;
    float sn = 0.f;
#pragma unroll
    for (int o = 0; o < 16; o++) { float v = g_s[idx * 16 + o]; sn = fmaf(v, v, sn); }
    out[idx] = sn / (1.f + sn);
}

// ---------------- launch ----------------
extern "C" void kernel_launch(void* const* d_in, const int* in_sizes, int n_in,
                              void* d_out, int out_size) {
    const float* x  = (const float*)d_in[0];
    const float* w1 = (const float*)d_in[1];
    const float* b1 = (const float*)d_in[2];
    const float* w2 = (const float*)d_in[3];
    const float* b2 = (const float*)d_in[4];
    const float* rw = (const float*)d_in[5];
    float* out = (float*)d_out;

    k_tr1<<<243, 256>>>(w1);
    k_tr2<<<8192, 256>>>(w2);
    k_conv1<<<dim3(24, 32), 256>>>(x, b1);
    k_prim<<<dim3(9, 16), 256>>>(b2);
    k_squash_u<<<(NB * NNODES + 255) / 256, 256>>>();
    k_priors<<<NNODES, 256>>>(rw);

    // iter 0: uniform probs (1/43 folded into squash scale)
    k_zero_s<<<172, 256>>>();
    k_reduce0<<<dim3(16, NB), 192>>>();
    k_squash_out<<<11, 256>>>(1.f / 43.f);    // also zeroes s

    // iter 1 (writes logits = delta; no pre-zero needed)
    k_iter<<<dim3(2, NB), 256>>>(1);
    k_squash_out<<<11, 256>>>(1.f);           // also zeroes s

    // iter 2 (final; reads logits, no store)
    k_iter<<<dim3(2, NB), 256>>>(0);
    k_final<<<11, 256>>>(out);
}

// round 6
// speedup vs baseline: 1.5537x; 1.5537x over previous
#include <cuda_runtime.h>
#include <cuda_fp16.h>
#include <math.h>

typedef unsigned long long ull;

// ---------------- problem constants ----------------
#define NB       64
#define NNODES   1296        // 16*81
#define NC       43
#define OD       16
#define CO_TIMES_OD 688      // 43*16
#define CO4      172         // 688/4

// packed f32x2 FMA (Blackwell sm_103a): two fp32 MACs per instruction, bit-exact fp32
#define FMA2(a,x,y) asm("fma.rn.f32x2 %0, %1, %2, %0;" : "+l"(a) : "l"(x), "l"(y))

static __device__ __forceinline__ float f2lo(ull v){ return __uint_as_float((unsigned)v); }
static __device__ __forceinline__ float f2hi(ull v){ return __uint_as_float((unsigned)(v>>32)); }
static __device__ __forceinline__ ull pack2(float w){ ull r; asm("mov.b64 %0, {%1, %1};" : "=l"(r) : "f"(w)); return r; }

// ---------------- device scratch ----------------
__device__ float  g_w1t[62208];                    // conv1 weights scalar: [(ci*9+ky)*9+kx][co]
__device__ float  g_w2t[2097152];                  // prim  weights scalar: [(g*8+ky)*8+kx][co]
__device__ float  g_h[NB * 256 * 24 * 24];         // conv1 output (relu'd)
__device__ float  g_u[NB * NNODES * 8];            // primary capsules (squashed in place)
__device__ ull    g_pri[(size_t)NB * NNODES * CO4];// priors, fp16x4 packed (114MB)
__device__ float  g_s[NB * CO_TIMES_OD];
__device__ float  g_caps0[NB * CO_TIMES_OD];       // outputs after iter 0
__device__ float  g_capsum[NB * CO_TIMES_OD];      // outputs0 + outputs1 (= logit carrier)

static __device__ __forceinline__ unsigned h2u(__half2 h){ return *reinterpret_cast<unsigned*>(&h); }
static __device__ __forceinline__ __half2 u2h(unsigned u){ return *reinterpret_cast<__half2*>(&u); }

static __device__ __forceinline__ float4 unpk(ull v) {
    float2 a = __half22float2(u2h((unsigned)v));
    float2 b = __half22float2(u2h((unsigned)(v >> 32)));
    return make_float4(a.x, a.y, b.x, b.y);
}

// ---------------- weight transposes (scalar, co-major for coalesced loads) ----------------
__global__ void k_tr1(const float* __restrict__ w) {
    int idx = blockIdx.x * 256 + threadIdx.x;
    if (idx >= 62208) return;
    int co = idx & 255; int r = idx >> 8;      // r = (ci*9+ky)*9+kx, 0..242
    int kx = r % 9; int t = r / 9; int ky = t % 9; int ci = t / 9;
    g_w1t[idx] = w[co * 243 + ci * 81 + ky * 9 + kx];
}
__global__ void k_tr2(const float* __restrict__ w) {
    int idx = blockIdx.x * 256 + threadIdx.x;   // 2,097,152 exact
    int co = idx & 127;
    int kx = (idx >> 7) & 7;
    int ky = (idx >> 10) & 7;
    int g  = idx >> 13;
    g_w2t[idx] = w[co * 16384 + g * 64 + ky * 8 + kx];
}

// ---------------- conv1: batch-paired f32x2, (64,3,32,32) -> (64,256,24,24) ----------------
__global__ __launch_bounds__(256, 2) void k_conv1(const float* __restrict__ x,
                                                  const float* __restrict__ bias) {
    int oy = blockIdx.x, bp = blockIdx.y;
    int b0 = bp, b1 = bp + 32;
    int co = threadIdx.x;
    __shared__ float2 xs[864];           // [3 ci][9 r][32 col], pair (b0,b1)
    for (int idx = co; idx < 864; idx += 256) {
        int ci = idx / 288, rem = idx - ci * 288;
        int r = rem >> 5, col = rem & 31;
        int off = (ci * 32 + oy + r) * 32 + col;
        xs[idx] = make_float2(x[b0 * 3072 + off], x[b1 * 3072 + off]);
    }
    __syncthreads();
    const ull* xsu = (const ull*)xs;
    float bv = bias[co];
#pragma unroll 1
    for (int h = 0; h < 2; h++) {        // two halves of the 24-wide output row
        ull acc[12];
#pragma unroll
        for (int i = 0; i < 12; i++) acc[i] = 0ull;
        for (int ci = 0; ci < 3; ci++) {
#pragma unroll
            for (int ky = 0; ky < 9; ky++) {
                ull in[20];
                const ulonglong2* ip = (const ulonglong2*)(xsu + ci * 288 + ky * 32 + h * 12);
#pragma unroll
                for (int j = 0; j < 10; j++) { ulonglong2 t = ip[j]; in[2*j] = t.x; in[2*j+1] = t.y; }
                const float* wp = &g_w1t[((ci * 9 + ky) * 9) * 256 + co];
                ull w[9];
#pragma unroll
                for (int kx = 0; kx < 9; kx++) w[kx] = pack2(wp[kx * 256]);
#pragma unroll
                for (int kx = 0; kx < 9; kx++)
#pragma unroll
                    for (int ox = 0; ox < 12; ox++)
                        FMA2(acc[ox], in[ox + kx], w[kx]);
            }
        }
        float* h0 = &g_h[((b0 * 256 + co) * 24 + oy) * 24 + h * 12];
        float* h1 = &g_h[((b1 * 256 + co) * 24 + oy) * 24 + h * 12];
#pragma unroll
        for (int ox = 0; ox < 12; ox++) {
            h0[ox] = fmaxf(f2lo(acc[ox]) + bv, 0.f);
            h1[ox] = fmaxf(f2hi(acc[ox]) + bv, 0.f);
        }
    }
}

// ---------------- prim conv: batch-paired f32x2, 8x8 s2 -> caps layout (round-4 version) ----------------
__global__ __launch_bounds__(256, 2) void k_prim(const float* __restrict__ bias) {
    int oy = blockIdx.x, bp = blockIdx.y;     // grid (9, 32)
    int b0 = bp, b1 = bp + 32;
    int tid = threadIdx.x;
    int kh = tid >> 7;          // K-range half
    int co = tid & 127;
    __shared__ float2 hs[6144];   // 48KB: [32 ci][8 r][24 col], pair (b0,b1)
    const ull* hsu = (const ull*)hs;
    ull acc[9];
#pragma unroll
    for (int i = 0; i < 9; i++) acc[i] = 0ull;

    for (int cc = 0; cc < 8; cc++) {      // 8 chunks of 32 input channels
        __syncthreads();
        for (int idx = tid; idx < 6144; idx += 256) {
            int ci = idx / 192, rem = idx - ci * 192;
            int r = rem / 24, col = rem - r * 24;
            int off = ((cc * 32 + ci) * 24 + 2 * oy + r) * 24 + col;
            hs[idx] = make_float2(g_h[b0 * 147456 + off], g_h[b1 * 147456 + off]);
        }
        __syncthreads();
        for (int cil = kh * 16; cil < kh * 16 + 16; cil++) {
            int g = cc * 32 + cil;
#pragma unroll
            for (int ky = 0; ky < 8; ky++) {
                ull in[24];
                const ulonglong2* ip = (const ulonglong2*)(hsu + cil * 192 + ky * 24);
#pragma unroll
                for (int j = 0; j < 12; j++) { ulonglong2 t = ip[j]; in[2*j] = t.x; in[2*j+1] = t.y; }
                const float* wp = &g_w2t[((g * 8 + ky) * 8) * 128 + co];
                ull w[8];
#pragma unroll
                for (int kx = 0; kx < 8; kx++) w[kx] = pack2(wp[kx * 128]);
#pragma unroll
                for (int kx = 0; kx < 8; kx++)
#pragma unroll
                    for (int ox = 0; ox < 9; ox++)
                        FMA2(acc[ox], in[2 * ox + kx], w[kx]);
            }
        }
    }
    __syncthreads();
    ull* cm = (ull*)hs;
    if (kh == 1) {
#pragma unroll
        for (int ox = 0; ox < 9; ox++) cm[co * 9 + ox] = acc[ox];
    }
    __syncthreads();
    if (kh == 0) {
        float bv = bias[co];
        int i = co >> 4, g2 = co & 15;
#pragma unroll
        for (int ox = 0; ox < 9; ox++) {
            ull o = cm[co * 9 + ox];
            float v0 = f2lo(acc[ox]) + f2lo(o) + bv;
            float v1 = f2hi(acc[ox]) + f2hi(o) + bv;
            int n = g2 * 81 + oy * 9 + ox;
            g_u[(b0 * NNODES + n) * 8 + i] = v0;
            g_u[(b1 * NNODES + n) * 8 + i] = v1;
        }
    }
}

// ---------------- squash primary capsules (dim 8, in place) ----------------
__global__ void k_squash_u() {
    int node = blockIdx.x * 256 + threadIdx.x;
    if (node >= NB * NNODES) return;
    float v[8]; float sn = 0.f;
#pragma unroll
    for (int i = 0; i < 8; i++) { v[i] = g_u[node * 8 + i]; sn = fmaf(v[i], v[i], sn); }
    float f = sqrtf(sn) / (1.f + sn);
#pragma unroll
    for (int i = 0; i < 8; i++) g_u[node * 8 + i] = v[i] * f;
}

// ---------------- priors[b,n,c,o] = sum_i u[b,n,i] * W[n,c,i,o]; store fp16x4 ----------------
__global__ __launch_bounds__(256) void k_priors(const float* __restrict__ route_w) {
    int n = blockIdx.x, tid = threadIdx.x;
    __shared__ float rw[NC * 8 * OD];   // 5504
    __shared__ float us[NB * 8];        // 512
    for (int idx = tid; idx < 5504; idx += 256) rw[idx] = route_w[n * 5504 + idx];
    for (int idx = tid; idx < 512; idx += 256) {
        int b = idx >> 3, i = idx & 7;
        us[idx] = g_u[(b * NNODES + n) * 8 + i];
    }
    __syncthreads();
    if (tid < CO4) {
        int c = tid >> 2;
        int obase = (tid & 3) * 4;
        const float* rwc = &rw[c * 128 + obase];
        for (int b = 0; b < NB; b++) {
            const float* ub = &us[b * 8];
            float4 sum = make_float4(0.f, 0.f, 0.f, 0.f);
#pragma unroll
            for (int i = 0; i < 8; i++) {
                float u = ub[i];
                sum.x = fmaf(u, rwc[i * 16 + 0], sum.x);
                sum.y = fmaf(u, rwc[i * 16 + 1], sum.y);
                sum.z = fmaf(u, rwc[i * 16 + 2], sum.z);
                sum.w = fmaf(u, rwc[i * 16 + 3], sum.w);
            }
            __half2 p01 = __floats2half2_rn(sum.x, sum.y);
            __half2 p23 = __floats2half2_rn(sum.z, sum.w);
            ull v = (ull)h2u(p01) | ((ull)h2u(p23) << 32);
            g_pri[(size_t)(b * NNODES + n) * CO4 + tid] = v;
        }
    }
}

// ---------------- zero s (start of pipeline only) ----------------
__global__ void k_zero_s() {
    int i = blockIdx.x * 256 + threadIdx.x;
    if (i < NB * CO_TIMES_OD) g_s[i] = 0.f;
}

// ---------------- iter0: s = sum_n priors (uniform probs folded into squash scale) ----------------
__global__ void k_reduce0() {
    int b = blockIdx.y, n0 = blockIdx.x * 81, tid = threadIdx.x;
    if (tid >= CO4) return;
    float4 acc = make_float4(0.f, 0.f, 0.f, 0.f);
    const ull* p = &g_pri[(size_t)(b * NNODES + n0) * CO4 + tid];
    for (int nn = 0; nn < 81; nn++) {
        float4 q = unpk(p[(size_t)nn * CO4]);
        acc.x += q.x; acc.y += q.y; acc.z += q.z; acc.w += q.w;
    }
    float* sp = &g_s[b * CO_TIMES_OD + tid * 4];
    atomicAdd(sp + 0, acc.x); atomicAdd(sp + 1, acc.y);
    atomicAdd(sp + 2, acc.z); atomicAdd(sp + 3, acc.w);
}

// ---------------- squash s -> caps0 (mode 0) or capsum = caps0 + squash(s) (mode 1); resets s ----------------
__global__ void k_squash_out(float scale, int mode) {
    int idx = blockIdx.x * 256 + threadIdx.x;
    if (idx >= NB * NC) return;
    float v[16]; float sn = 0.f;
#pragma unroll
    for (int o = 0; o < 16; o++) { v[o] = g_s[idx * 16 + o] * scale; sn = fmaf(v[o], v[o], sn); }
    float f = sqrtf(sn) / (1.f + sn);
#pragma unroll
    for (int o = 0; o < 16; o++) {
        float cap = v[o] * f;
        if (mode == 0) g_caps0[idx * 16 + o] = cap;
        else           g_capsum[idx * 16 + o] = g_caps0[idx * 16 + o] + cap;
        g_s[idx * 16 + o] = 0.f;
    }
}

// ---------------- routing iteration (no logits array):
//   softmax over classes of (priors . caps_sel), then s += probs * priors.
//   sel=0: caps0 (iter 1);  sel=1: caps0+caps1 (iter 2). Warp = node, lane = class. ----------------
__global__ __launch_bounds__(256) void k_iter(int sel) {
    int b = blockIdx.y;
    int wid = threadIdx.x >> 5;
    int lane = threadIdx.x & 31;
    int nbase = blockIdx.x * 81;          // grid.x = 16
    int c1 = lane;
    bool has2 = lane < (NC - 32);         // lanes 0..10 carry class 32+lane
    int c2 = lane + 32;

    __shared__ float s_acc[CO_TIMES_OD];
    for (int i = threadIdx.x; i < CO_TIMES_OD; i += 256) s_acc[i] = 0.f;

    const float* cb = sel ? &g_capsum[b * CO_TIMES_OD] : &g_caps0[b * CO_TIMES_OD];
    float cap1[16], cap2[16];
#pragma unroll
    for (int o = 0; o < 16; o++) cap1[o] = cb[c1 * OD + o];
#pragma unroll
    for (int o = 0; o < 16; o++) cap2[o] = has2 ? cb[c2 * OD + o] : 0.f;

    float acc1[16], acc2[16];
#pragma unroll
    for (int o = 0; o < 16; o++) { acc1[o] = 0.f; acc2[o] = 0.f; }
    __syncthreads();

    for (int nn = wid; nn < 81; nn += 8) {
        int n = nbase + nn;
        const ull* pp = &g_pri[((size_t)b * NNODES + n) * CO4];
        float pr1[16], pr2[16];
        {
            ulonglong2 q0 = *(const ulonglong2*)(pp + 4 * c1);
            ulonglong2 q1 = *(const ulonglong2*)(pp + 4 * c1 + 2);
            float4 a0 = unpk(q0.x), a1 = unpk(q0.y), a2 = unpk(q1.x), a3 = unpk(q1.y);
            pr1[0]=a0.x; pr1[1]=a0.y; pr1[2]=a0.z; pr1[3]=a0.w;
            pr1[4]=a1.x; pr1[5]=a1.y; pr1[6]=a1.z; pr1[7]=a1.w;
            pr1[8]=a2.x; pr1[9]=a2.y; pr1[10]=a2.z; pr1[11]=a2.w;
            pr1[12]=a3.x; pr1[13]=a3.y; pr1[14]=a3.z; pr1[15]=a3.w;
        }
        if (has2) {
            ulonglong2 q0 = *(const ulonglong2*)(pp + 4 * c2);
            ulonglong2 q1 = *(const ulonglong2*)(pp + 4 * c2 + 2);
            float4 a0 = unpk(q0.x), a1 = unpk(q0.y), a2 = unpk(q1.x), a3 = unpk(q1.y);
            pr2[0]=a0.x; pr2[1]=a0.y; pr2[2]=a0.z; pr2[3]=a0.w;
            pr2[4]=a1.x; pr2[5]=a1.y; pr2[6]=a1.z; pr2[7]=a1.w;
            pr2[8]=a2.x; pr2[9]=a2.y; pr2[10]=a2.z; pr2[11]=a2.w;
            pr2[12]=a3.x; pr2[13]=a3.y; pr2[14]=a3.z; pr2[15]=a3.w;
        } else {
#pragma unroll
            for (int o = 0; o < 16; o++) pr2[o] = 0.f;
        }
        float l1 = 0.f, l2 = 0.f;
#pragma unroll
        for (int o = 0; o < 16; o++) { l1 = fmaf(pr1[o], cap1[o], l1); l2 = fmaf(pr2[o], cap2[o], l2); }
        if (!has2) l2 = -1e30f;

        float mloc = fmaxf(l1, l2);
#pragma unroll
        for (int off = 16; off; off >>= 1) mloc = fmaxf(mloc, __shfl_xor_sync(0xffffffffu, mloc, off));
        float e1 = __expf(l1 - mloc);
        float e2 = has2 ? __expf(l2 - mloc) : 0.f;
        float ss = e1 + e2;
#pragma unroll
        for (int off = 16; off; off >>= 1) ss += __shfl_xor_sync(0xffffffffu, ss, off);
        float inv = 1.f / ss;
        float p1 = e1 * inv, p2 = e2 * inv;
#pragma unroll
        for (int o = 0; o < 16; o++) { acc1[o] = fmaf(p1, pr1[o], acc1[o]); acc2[o] = fmaf(p2, pr2[o], acc2[o]); }
    }
    // block-level accumulate in smem (8-way contention per address at most)
#pragma unroll
    for (int o = 0; o < 16; o++) atomicAdd(&s_acc[c1 * OD + o], acc1[o]);
    if (has2) {
#pragma unroll
        for (int o = 0; o < 16; o++) atomicAdd(&s_acc[c2 * OD + o], acc2[o]);
    }
    __syncthreads();
    // one flush per block: 172 threads x 4 atomics
    if (threadIdx.x < CO4) {
        float4 a = *(const float4*)&s_acc[threadIdx.x * 4];
        float* sp = &g_s[b * CO_TIMES_OD + threadIdx.x * 4];
        atomicAdd(sp + 0, a.x); atomicAdd(sp + 1, a.y);
        atomicAdd(sp + 2, a.z); atomicAdd(sp + 3, a.w);
    }
}

// ---------------- final: scores = ||squash(s)|| = sn/(1+sn) ----------------
__global__ void k_final(float* __restrict__ out) {
    int idx = blockIdx.x * 256 + threadIdx.x;
    if (idx >= NB * NC) return;
    float sn = 0.f;
#pragma unroll
    for (int o = 0; o < 16; o++) { float v = g_s[idx * 16 + o]; sn = fmaf(v, v, sn); }
    out[idx] = sn / (1.f + sn);
}

// ---------------- launch ----------------
extern "C" void kernel_launch(void* const* d_in, const int* in_sizes, int n_in,
                              void* d_out, int out_size) {
    const float* x  = (const float*)d_in[0];
    const float* w1 = (const float*)d_in[1];
    const float* b1 = (const float*)d_in[2];
    const float* w2 = (const float*)d_in[3];
    const float* b2 = (const float*)d_in[4];
    const float* rw = (const float*)d_in[5];
    float* out = (float*)d_out;

    k_tr1<<<243, 256>>>(w1);
    k_tr2<<<8192, 256>>>(w2);
    k_conv1<<<dim3(24, 32), 256>>>(x, b1);
    k_prim<<<dim3(9, 32), 256>>>(b2);
    k_squash_u<<<(NB * NNODES + 255) / 256, 256>>>();
    k_priors<<<NNODES, 256>>>(rw);

    // iter 0: uniform probs (1/43 folded into squash scale) -> caps0
    k_zero_s<<<172, 256>>>();
    k_reduce0<<<dim3(16, NB), 192>>>();
    k_squash_out<<<11, 256>>>(1.f / 43.f, 0);    // writes caps0, zeroes s

    // iter 1: softmax(pr . caps0) -> s -> capsum = caps0 + squash(s)
    k_iter<<<dim3(16, NB), 256>>>(0);
    k_squash_out<<<11, 256>>>(1.f, 1);           // writes capsum, zeroes s

    // iter 2: softmax(pr . capsum) -> s -> scores
    k_iter<<<dim3(16, NB), 256>>>(1);
    k_final<<<11, 256>>>(out);
}

// round 7
// speedup vs baseline: 1.6543x; 1.0647x over previous
#include <cuda_runtime.h>
#include <cuda_fp16.h>
#include <math.h>

typedef unsigned long long ull;

// ---------------- problem constants ----------------
#define NB       64
#define NNODES   1296        // 16*81
#define NC       43
#define OD       16
#define CO_TIMES_OD 688      // 43*16
#define CO4      172         // 688/4

// packed f32x2 FMA (Blackwell sm_103a): two fp32 MACs per instruction, bit-exact fp32
#define FMA2(a,x,y) asm("fma.rn.f32x2 %0, %1, %2, %0;" : "+l"(a) : "l"(x), "l"(y))

#define CPASYNC16(dst_u32, src_ptr) \
    asm volatile("cp.async.cg.shared.global [%0], [%1], 16;" :: "r"(dst_u32), "l"(src_ptr))
#define CPCOMMIT()  asm volatile("cp.async.commit_group;" ::: "memory")
#define CPWAIT0()   asm volatile("cp.async.wait_group 0;" ::: "memory")

static __device__ __forceinline__ float f2lo(ull v){ return __uint_as_float((unsigned)v); }
static __device__ __forceinline__ float f2hi(ull v){ return __uint_as_float((unsigned)(v>>32)); }
static __device__ __forceinline__ ull pack2(float w){ ull r; asm("mov.b64 %0, {%1, %1};" : "=l"(r) : "f"(w)); return r; }

// ---------------- device scratch ----------------
__device__ float  g_w1t[62208];                    // conv1 weights scalar: [(ci*9+ky)*9+kx][co]
__device__ float  g_w2t[2097152];                  // prim  weights scalar: [(g*8+ky)*8+kx][co]
__device__ __align__(16) float2 g_h2[32 * 256 * 24 * 24];  // conv1 output, batch-paired (bp, bp+32)
__device__ float  g_u[NB * NNODES * 8];            // primary capsules (squashed in place)
__device__ ull    g_pri[(size_t)NB * NNODES * CO4];// priors, fp16x4 packed (114MB)
__device__ float  g_s[NB * CO_TIMES_OD];
__device__ float  g_caps0[NB * CO_TIMES_OD];       // outputs after iter 0
__device__ float  g_capsum[NB * CO_TIMES_OD];      // outputs0 + outputs1 (= logit carrier)

static __device__ __forceinline__ unsigned h2u(__half2 h){ return *reinterpret_cast<unsigned*>(&h); }
static __device__ __forceinline__ __half2 u2h(unsigned u){ return *reinterpret_cast<__half2*>(&u); }

static __device__ __forceinline__ float4 unpk(ull v) {
    float2 a = __half22float2(u2h((unsigned)v));
    float2 b = __half22float2(u2h((unsigned)(v >> 32)));
    return make_float4(a.x, a.y, b.x, b.y);
}

// ---------------- weight transposes (scalar, co-major for coalesced loads) ----------------
__global__ void k_tr1(const float* __restrict__ w) {
    int idx = blockIdx.x * 256 + threadIdx.x;
    if (idx >= 62208) return;
    int co = idx & 255; int r = idx >> 8;      // r = (ci*9+ky)*9+kx, 0..242
    int kx = r % 9; int t = r / 9; int ky = t % 9; int ci = t / 9;
    g_w1t[idx] = w[co * 243 + ci * 81 + ky * 9 + kx];
}
__global__ void k_tr2(const float* __restrict__ w) {
    int idx = blockIdx.x * 256 + threadIdx.x;   // 2,097,152 exact
    int co = idx & 127;
    int kx = (idx >> 7) & 7;
    int ky = (idx >> 10) & 7;
    int g  = idx >> 13;
    g_w2t[idx] = w[co * 16384 + g * 64 + ky * 8 + kx];
}

// ---------------- conv1: batch-paired f32x2, (64,3,32,32) -> paired float2 output ----------------
__global__ __launch_bounds__(256, 2) void k_conv1(const float* __restrict__ x,
                                                  const float* __restrict__ bias) {
    int oy = blockIdx.x, bp = blockIdx.y;
    int b0 = bp, b1 = bp + 32;
    int co = threadIdx.x;
    __shared__ float2 xs[864];           // [3 ci][9 r][32 col], pair (b0,b1)
    for (int idx = co; idx < 864; idx += 256) {
        int ci = idx / 288, rem = idx - ci * 288;
        int r = rem >> 5, col = rem & 31;
        int off = (ci * 32 + oy + r) * 32 + col;
        xs[idx] = make_float2(x[b0 * 3072 + off], x[b1 * 3072 + off]);
    }
    __syncthreads();
    const ull* xsu = (const ull*)xs;
    float bv = bias[co];
#pragma unroll 1
    for (int h = 0; h < 2; h++) {        // two halves of the 24-wide output row
        ull acc[12];
#pragma unroll
        for (int i = 0; i < 12; i++) acc[i] = 0ull;
        for (int ci = 0; ci < 3; ci++) {
#pragma unroll
            for (int ky = 0; ky < 9; ky++) {
                ull in[20];
                const ulonglong2* ip = (const ulonglong2*)(xsu + ci * 288 + ky * 32 + h * 12);
#pragma unroll
                for (int j = 0; j < 10; j++) { ulonglong2 t = ip[j]; in[2*j] = t.x; in[2*j+1] = t.y; }
                const float* wp = &g_w1t[((ci * 9 + ky) * 9) * 256 + co];
                ull w[9];
#pragma unroll
                for (int kx = 0; kx < 9; kx++) w[kx] = pack2(wp[kx * 256]);
#pragma unroll
                for (int kx = 0; kx < 9; kx++)
#pragma unroll
                    for (int ox = 0; ox < 12; ox++)
                        FMA2(acc[ox], in[ox + kx], w[kx]);
            }
        }
        float2* hp = &g_h2[((bp * 256 + co) * 24 + oy) * 24 + h * 12];
#pragma unroll
        for (int ox = 0; ox < 12; ox++)
            hp[ox] = make_float2(fmaxf(f2lo(acc[ox]) + bv, 0.f),
                                 fmaxf(f2hi(acc[ox]) + bv, 0.f));
    }
}

// ---------------- prim conv: cp.async double-buffered, batch-paired f32x2 ----------------
__global__ __launch_bounds__(256, 2) void k_prim(const float* __restrict__ bias) {
    int oy = blockIdx.x, bp = blockIdx.y;     // grid (9, 32)
    int b0 = bp, b1 = bp + 32;
    int tid = threadIdx.x;
    int kh = tid >> 7;          // K-range half
    int co = tid & 127;
    // two 24KB buffers: [16 ci][8 r][24 col] float2 each
    __shared__ __align__(16) float2 hs[2][3072];
    unsigned sb[2];
    sb[0] = (unsigned)__cvta_generic_to_shared(&hs[0][0]);
    sb[1] = (unsigned)__cvta_generic_to_shared(&hs[1][0]);

    // per-thread cp.async op list: q = tid + j*256, q in [0,1536)
    // q -> c16 (0..11), r (0..7), ci (0..15)
    int qc16[6], qr[6], qci[6];
#pragma unroll
    for (int j = 0; j < 6; j++) {
        int q = tid + j * 256;
        qc16[j] = q % 12; int t2 = q / 12;
        qr[j] = t2 & 7; qci[j] = t2 >> 3;
    }

    ull acc[9];
#pragma unroll
    for (int i = 0; i < 9; i++) acc[i] = 0ull;

    // prologue: load chunk 0 into buf 0
#pragma unroll
    for (int j = 0; j < 6; j++) {
        const float2* src = &g_h2[((size_t)(bp * 256 + qci[j]) * 24 + 2 * oy + qr[j]) * 24 + qc16[j] * 2];
        unsigned dst = sb[0] + (unsigned)((qci[j] * 192 + qr[j] * 24 + qc16[j] * 2) * 8);
        CPASYNC16(dst, src);
    }
    CPCOMMIT(); CPWAIT0();
    __syncthreads();

#pragma unroll 1
    for (int cc = 0; cc < 16; cc++) {      // 16 chunks of 16 input channels
        // issue copy of next chunk into the other buffer
        if (cc < 15) {
            int nb = (cc + 1) & 1;
#pragma unroll
            for (int j = 0; j < 6; j++) {
                const float2* src = &g_h2[((size_t)(bp * 256 + (cc + 1) * 16 + qci[j]) * 24 + 2 * oy + qr[j]) * 24 + qc16[j] * 2];
                unsigned dst = sb[nb] + (unsigned)((qci[j] * 192 + qr[j] * 24 + qc16[j] * 2) * 8);
                CPASYNC16(dst, src);
            }
            CPCOMMIT();
        }
        // compute on current buffer
        const ull* hsu = (const ull*)&hs[cc & 1][0];
        for (int cil = kh * 8; cil < kh * 8 + 8; cil++) {
            int g = cc * 16 + cil;
#pragma unroll
            for (int ky = 0; ky < 8; ky++) {
                ull in[24];
                const ulonglong2* ip = (const ulonglong2*)(hsu + cil * 192 + ky * 24);
#pragma unroll
                for (int j = 0; j < 12; j++) { ulonglong2 t = ip[j]; in[2*j] = t.x; in[2*j+1] = t.y; }
                const float* wp = &g_w2t[((g * 8 + ky) * 8) * 128 + co];
                ull w[8];
#pragma unroll
                for (int kx = 0; kx < 8; kx++) w[kx] = pack2(wp[kx * 128]);
#pragma unroll
                for (int kx = 0; kx < 8; kx++)
#pragma unroll
                    for (int ox = 0; ox < 9; ox++)
                        FMA2(acc[ox], in[2 * ox + kx], w[kx]);
            }
        }
        if (cc < 15) {
            CPWAIT0();
            __syncthreads();
        }
    }
    __syncthreads();
    ull* cm = (ull*)&hs[0][0];
    if (kh == 1) {
#pragma unroll
        for (int ox = 0; ox < 9; ox++) cm[co * 9 + ox] = acc[ox];
    }
    __syncthreads();
    if (kh == 0) {
        float bv = bias[co];
        int i = co >> 4, g2 = co & 15;
#pragma unroll
        for (int ox = 0; ox < 9; ox++) {
            ull o = cm[co * 9 + ox];
            float v0 = f2lo(acc[ox]) + f2lo(o) + bv;
            float v1 = f2hi(acc[ox]) + f2hi(o) + bv;
            int n = g2 * 81 + oy * 9 + ox;
            g_u[(b0 * NNODES + n) * 8 + i] = v0;
            g_u[(b1 * NNODES + n) * 8 + i] = v1;
        }
    }
}

// ---------------- squash primary capsules (dim 8, in place) ----------------
__global__ void k_squash_u() {
    int node = blockIdx.x * 256 + threadIdx.x;
    if (node >= NB * NNODES) return;
    float v[8]; float sn = 0.f;
#pragma unroll
    for (int i = 0; i < 8; i++) { v[i] = g_u[node * 8 + i]; sn = fmaf(v[i], v[i], sn); }
    float f = sqrtf(sn) / (1.f + sn);
#pragma unroll
    for (int i = 0; i < 8; i++) g_u[node * 8 + i] = v[i] * f;
}

// ---------------- priors[b,n,c,o] = sum_i u[b,n,i] * W[n,c,i,o]; store fp16x4 ----------------
__global__ __launch_bounds__(192) void k_priors(const float* __restrict__ route_w) {
    int n = blockIdx.x, by = blockIdx.y, tid = threadIdx.x;
    __shared__ float rw[NC * 8 * OD];   // 5504
    __shared__ float us[32 * 8];        // 256
    for (int idx = tid; idx < 5504; idx += 192) rw[idx] = route_w[n * 5504 + idx];
    for (int idx = tid; idx < 256; idx += 192) {
        int b = (idx >> 3) + by * 32, i = idx & 7;
        us[idx] = g_u[(b * NNODES + n) * 8 + i];
    }
    __syncthreads();
    if (tid < CO4) {
        int c = tid >> 2;
        int obase = (tid & 3) * 4;
        const float* rwc = &rw[c * 128 + obase];
        for (int bl = 0; bl < 32; bl++) {
            int b = by * 32 + bl;
            const float* ub = &us[bl * 8];
            float4 sum = make_float4(0.f, 0.f, 0.f, 0.f);
#pragma unroll
            for (int i = 0; i < 8; i++) {
                float u = ub[i];
                sum.x = fmaf(u, rwc[i * 16 + 0], sum.x);
                sum.y = fmaf(u, rwc[i * 16 + 1], sum.y);
                sum.z = fmaf(u, rwc[i * 16 + 2], sum.z);
                sum.w = fmaf(u, rwc[i * 16 + 3], sum.w);
            }
            __half2 p01 = __floats2half2_rn(sum.x, sum.y);
            __half2 p23 = __floats2half2_rn(sum.z, sum.w);
            ull v = (ull)h2u(p01) | ((ull)h2u(p23) << 32);
            g_pri[(size_t)(b * NNODES + n) * CO4 + tid] = v;
        }
    }
}

// ---------------- zero s (start of pipeline only) ----------------
__global__ void k_zero_s() {
    int i = blockIdx.x * 256 + threadIdx.x;
    if (i < NB * CO_TIMES_OD) g_s[i] = 0.f;
}

// ---------------- iter0: s = sum_n priors (uniform probs folded into squash scale) ----------------
__global__ void k_reduce0() {
    int b = blockIdx.y, n0 = blockIdx.x * 81, tid = threadIdx.x;
    if (tid >= CO4) return;
    float4 acc = make_float4(0.f, 0.f, 0.f, 0.f);
    const ull* p = &g_pri[(size_t)(b * NNODES + n0) * CO4 + tid];
    for (int nn = 0; nn < 81; nn++) {
        float4 q = unpk(p[(size_t)nn * CO4]);
        acc.x += q.x; acc.y += q.y; acc.z += q.z; acc.w += q.w;
    }
    float* sp = &g_s[b * CO_TIMES_OD + tid * 4];
    atomicAdd(sp + 0, acc.x); atomicAdd(sp + 1, acc.y);
    atomicAdd(sp + 2, acc.z); atomicAdd(sp + 3, acc.w);
}

// ---------------- squash s -> caps0 (mode 0) or capsum = caps0 + squash(s) (mode 1); resets s ----------------
__global__ void k_squash_out(float scale, int mode) {
    int idx = blockIdx.x * 256 + threadIdx.x;
    if (idx >= NB * NC) return;
    float v[16]; float sn = 0.f;
#pragma unroll
    for (int o = 0; o < 16; o++) { v[o] = g_s[idx * 16 + o] * scale; sn = fmaf(v[o], v[o], sn); }
    float f = sqrtf(sn) / (1.f + sn);
#pragma unroll
    for (int o = 0; o < 16; o++) {
        float cap = v[o] * f;
        if (mode == 0) g_caps0[idx * 16 + o] = cap;
        else           g_capsum[idx * 16 + o] = g_caps0[idx * 16 + o] + cap;
        g_s[idx * 16 + o] = 0.f;
    }
}

// ---------------- routing iteration (no logits array):
//   softmax over classes of (priors . caps_sel), then s += probs * priors. ----------------
__global__ __launch_bounds__(256) void k_iter(int sel) {
    int b = blockIdx.y;
    int wid = threadIdx.x >> 5;
    int lane = threadIdx.x & 31;
    int nbase = blockIdx.x * 81;          // grid.x = 16
    int c1 = lane;
    bool has2 = lane < (NC - 32);         // lanes 0..10 carry class 32+lane
    int c2 = lane + 32;

    __shared__ float s_acc[CO_TIMES_OD];
    for (int i = threadIdx.x; i < CO_TIMES_OD; i += 256) s_acc[i] = 0.f;

    const float* cb = sel ? &g_capsum[b * CO_TIMES_OD] : &g_caps0[b * CO_TIMES_OD];
    float cap1[16], cap2[16];
#pragma unroll
    for (int o = 0; o < 16; o++) cap1[o] = cb[c1 * OD + o];
#pragma unroll
    for (int o = 0; o < 16; o++) cap2[o] = has2 ? cb[c2 * OD + o] : 0.f;

    float acc1[16], acc2[16];
#pragma unroll
    for (int o = 0; o < 16; o++) { acc1[o] = 0.f; acc2[o] = 0.f; }
    __syncthreads();

    for (int nn = wid; nn < 81; nn += 8) {
        int n = nbase + nn;
        const ull* pp = &g_pri[((size_t)b * NNODES + n) * CO4];
        float pr1[16], pr2[16];
        {
            ulonglong2 q0 = *(const ulonglong2*)(pp + 4 * c1);
            ulonglong2 q1 = *(const ulonglong2*)(pp + 4 * c1 + 2);
            float4 a0 = unpk(q0.x), a1 = unpk(q0.y), a2 = unpk(q1.x), a3 = unpk(q1.y);
            pr1[0]=a0.x; pr1[1]=a0.y; pr1[2]=a0.z; pr1[3]=a0.w;
            pr1[4]=a1.x; pr1[5]=a1.y; pr1[6]=a1.z; pr1[7]=a1.w;
            pr1[8]=a2.x; pr1[9]=a2.y; pr1[10]=a2.z; pr1[11]=a2.w;
            pr1[12]=a3.x; pr1[13]=a3.y; pr1[14]=a3.z; pr1[15]=a3.w;
        }
        if (has2) {
            ulonglong2 q0 = *(const ulonglong2*)(pp + 4 * c2);
            ulonglong2 q1 = *(const ulonglong2*)(pp + 4 * c2 + 2);
            float4 a0 = unpk(q0.x), a1 = unpk(q0.y), a2 = unpk(q1.x), a3 = unpk(q1.y);
            pr2[0]=a0.x; pr2[1]=a0.y; pr2[2]=a0.z; pr2[3]=a0.w;
            pr2[4]=a1.x; pr2[5]=a1.y; pr2[6]=a1.z; pr2[7]=a1.w;
            pr2[8]=a2.x; pr2[9]=a2.y; pr2[10]=a2.z; pr2[11]=a2.w;
            pr2[12]=a3.x; pr2[13]=a3.y; pr2[14]=a3.z; pr2[15]=a3.w;
        } else {
#pragma unroll
            for (int o = 0; o < 16; o++) pr2[o] = 0.f;
        }
        float l1 = 0.f, l2 = 0.f;
#pragma unroll
        for (int o = 0; o < 16; o++) { l1 = fmaf(pr1[o], cap1[o], l1); l2 = fmaf(pr2[o], cap2[o], l2); }
        if (!has2) l2 = -1e30f;

        float mloc = fmaxf(l1, l2);
#pragma unroll
        for (int off = 16; off; off >>= 1) mloc = fmaxf(mloc, __shfl_xor_sync(0xffffffffu, mloc, off));
        float e1 = __expf(l1 - mloc);
        float e2 = has2 ? __expf(l2 - mloc) : 0.f;
        float ss = e1 + e2;
#pragma unroll
        for (int off = 16; off; off >>= 1) ss += __shfl_xor_sync(0xffffffffu, ss, off);
        float inv = 1.f / ss;
        float p1 = e1 * inv, p2 = e2 * inv;
#pragma unroll
        for (int o = 0; o < 16; o++) { acc1[o] = fmaf(p1, pr1[o], acc1[o]); acc2[o] = fmaf(p2, pr2[o], acc2[o]); }
    }
#pragma unroll
    for (int o = 0; o < 16; o++) atomicAdd(&s_acc[c1 * OD + o], acc1[o]);
    if (has2) {
#pragma unroll
        for (int o = 0; o < 16; o++) atomicAdd(&s_acc[c2 * OD + o], acc2[o]);
    }
    __syncthreads();
    if (threadIdx.x < CO4) {
        float4 a = *(const float4*)&s_acc[threadIdx.x * 4];
        float* sp = &g_s[b * CO_TIMES_OD + threadIdx.x * 4];
        atomicAdd(sp + 0, a.x); atomicAdd(sp + 1, a.y);
        atomicAdd(sp + 2, a.z); atomicAdd(sp + 3, a.w);
    }
}

// ---------------- final: scores = ||squash(s)|| = sn/(1+sn) ----------------
__global__ void k_final(float* __restrict__ out) {
    int idx = blockIdx.x * 256 + threadIdx.x;
    if (idx >= NB * NC) return;
    float sn = 0.f;
#pragma unroll
    for (int o = 0; o < 16; o++) { float v = g_s[idx * 16 + o]; sn = fmaf(v, v, sn); }
    out[idx] = sn / (1.f + sn);
}

// ---------------- launch ----------------
extern "C" void kernel_launch(void* const* d_in, const int* in_sizes, int n_in,
                              void* d_out, int out_size) {
    const float* x  = (const float*)d_in[0];
    const float* w1 = (const float*)d_in[1];
    const float* b1 = (const float*)d_in[2];
    const float* w2 = (const float*)d_in[3];
    const float* b2 = (const float*)d_in[4];
    const float* rw = (const float*)d_in[5];
    float* out = (float*)d_out;

    k_tr1<<<243, 256>>>(w1);
    k_tr2<<<8192, 256>>>(w2);
    k_conv1<<<dim3(24, 32), 256>>>(x, b1);
    k_prim<<<dim3(9, 32), 256>>>(b2);
    k_squash_u<<<(NB * NNODES + 255) / 256, 256>>>();
    k_priors<<<dim3(NNODES, 2), 192>>>(rw);

    // iter 0: uniform probs (1/43 folded into squash scale) -> caps0
    k_zero_s<<<172, 256>>>();
    k_reduce0<<<dim3(16, NB), 192>>>();
    k_squash_out<<<11, 256>>>(1.f / 43.f, 0);    // writes caps0, zeroes s

    // iter 1: softmax(pr . caps0) -> s -> capsum = caps0 + squash(s)
    k_iter<<<dim3(16, NB), 256>>>(0);
    k_squash_out<<<11, 256>>>(1.f, 1);           // writes capsum, zeroes s

    // iter 2: softmax(pr . capsum) -> s -> scores
    k_iter<<<dim3(16, NB), 256>>>(1);
    k_final<<<11, 256>>>(out);
}